// round 4
// baseline (speedup 1.0000x reference)
#include <cuda_runtime.h>
#include <math.h>

// StickBreaking: B=32 batches, N=512. out[b,m,n] via row-serial stick-breaking.
// One CTA per batch; inherently serial N^2 chain per batch -> latency-bound.

#define NB 32
#define NN 512
#define NWARP (NN / 32)

__global__ __launch_bounds__(NN, 1)
void stickbreak_kernel(const float* __restrict__ x,
                       const float* __restrict__ xm,
                       float* __restrict__ out)
{
    __shared__ float  rev[NN];    // fut, reversed order (for suffix scan)
    __shared__ float  sfx[NN];    // inclusive scan of rev
    __shared__ float  wsum[NWARP];
    __shared__ float4 pk[NN];     // {M1, B1, mfm, c1} per column
    __shared__ float  rowp[NN];   // this row's outputs p[n]

    const int b    = blockIdx.x;
    const int tid  = threadIdx.x;
    const int lane = tid & 31;
    const int warp = tid >> 5;

    const float* xb = x  + (size_t)b * NN * NN;
    const float* mb = xm + (size_t)b * NN * NN;
    float*       ob = out + (size_t)b * NN * NN;

    // column sum owned by this thread's column (tid)
    float cs = 0.0f;

    // preload row 0
    float xv = xb[tid];
    float mv = mb[tid];

    for (int m = 0; m < NN; ++m) {
        // ---- parallel per-row precompute ----
        float bval = 1.0f / (1.0f + expf(-xv));        // sigmoid
        float fut  = fmaxf(0.0f, mv - cs);             // max(0, mask - col_sum)

        rev[NN - 1 - tid] = fut;                       // reversed for suffix sum
        __syncthreads();

        // block inclusive scan of rev (Kogge-Stone within warp + warp offsets)
        float v = rev[tid];
        #pragma unroll
        for (int d = 1; d < 32; d <<= 1) {
            float t = __shfl_up_sync(0xffffffffu, v, d);
            if (lane >= d) v += t;
        }
        if (lane == 31) wsum[warp] = v;
        __syncthreads();
        if (warp == 0) {
            float w = (lane < NWARP) ? wsum[lane] : 0.0f;
            #pragma unroll
            for (int d = 1; d < NWARP; d <<= 1) {
                float t = __shfl_up_sync(0xffffffffu, w, d);
                if (lane >= d) w += t;
            }
            if (lane < NWARP) wsum[lane] = w;
        }
        __syncthreads();
        float incl = v + ((warp > 0) ? wsum[warp - 1] : 0.0f);
        sfx[tid] = incl;
        __syncthreads();

        // mfm[n] = sum_{j>n} fut[j]  (exclusive reverse cumsum, exact order)
        float mfm = sfx[NN - 1 - tid] - fut;

        float M1 = mv * (1.0f - bval);   // (1-b)*mask
        float B1 = mv * bval;            // b*mask
        pk[tid] = make_float4(M1, B1, mfm, 1.0f - cs);
        __syncthreads();

        // prefetch next row while the serial scan runs (issued before barrier)
        if (m + 1 < NN) {
            xv = xb[(m + 1) * NN + tid];
            mv = mb[(m + 1) * NN + tid];
        }

        // ---- serial within-row scan: the only true dependency chain ----
        if (tid == 0) {
            float r = 1.0f;   // r = 1 - row_sum
            #pragma unroll 8
            for (int n = 0; n < NN; ++n) {
                float4 f  = pk[n];
                float  a  = fmaxf(r - f.z, 0.0f);         // max(0, 1 - s - mfm)
                float  u  = fminf(r, f.w);                 // min(1-s, 1-cs)
                float  rn = fmaf(-f.x, a, fmaf(-f.y, u, r)); // r - M1*a - B1*u
                rowp[n] = r - rn;                          // p = M1*a + B1*u
                r = rn;
            }
        }
        __syncthreads();

        // ---- consume row: update column sums, write output ----
        float p = rowp[tid];
        cs += p;
        ob[m * NN + tid] = p;
        // no trailing barrier needed: next iter's first write (rev) is a
        // different array, and pk/rowp rewrites are fenced by later barriers.
    }
}

extern "C" void kernel_launch(void* const* d_in, const int* in_sizes, int n_in,
                              void* d_out, int out_size)
{
    const float* x  = (const float*)d_in[0];
    const float* xm = (const float*)d_in[1];
    float* out = (float*)d_out;
    (void)in_sizes; (void)n_in; (void)out_size;

    stickbreak_kernel<<<NB, NN>>>(x, xm, out);
}

// round 6
// speedup vs baseline: 2.3992x; 2.3992x over previous
#include <cuda_runtime.h>
#include <math.h>

// StickBreaking: B=32, N=512. One CTA per batch; the N^2 stick-breaking
// recurrence is a single dependent FP chain per batch -> latency-bound.
// This version keeps the per-iteration chain to ~14 cycles:
//   - smem loads taken off the chain via ping-pong register prefetch
//   - algebraic restructure: rn = max(c0*r, r-bc) + min(mz - M1*r, 0)

#define NB 32
#define NN 512
#define NWARP (NN / 32)

__global__ __launch_bounds__(NN, 1)
void stickbreak_kernel(const float* __restrict__ x,
                       const float* __restrict__ xm,
                       float* __restrict__ out)
{
    __shared__ float  wsum[NWARP];     // per-warp totals of fut
    __shared__ float  wtail[NWARP];    // exclusive suffix over warp totals
    __shared__ float4 pk[NN + 8];      // {c0, bc, mz, M1}; padded for prefetch
    __shared__ float  rowp[NN];        // this row's outputs p[n]

    const int b    = blockIdx.x;
    const int tid  = threadIdx.x;
    const int lane = tid & 31;
    const int warp = tid >> 5;

    const float* xb = x  + (size_t)b * NN * NN;
    const float* mb = xm + (size_t)b * NN * NN;
    float*       ob = out + (size_t)b * NN * NN;

    float cs = 0.0f;                   // column sum for column tid

    // row 0: load + cs-independent precompute
    float xv = xb[tid];
    float mv = mb[tid];
    float sg = 1.0f / (1.0f + expf(-xv));
    float B1 = mv * sg;                // b*mask
    float M1 = mv - B1;                // (1-b)*mask
    float c0 = 1.0f - B1;

    for (int m = 0; m < NN; ++m) {
        // ---- fut + exact suffix sums (mfm) ----
        float fut = fmaxf(0.0f, mv - cs);

        // inclusive suffix scan within warp (shfl_down Kogge-Stone)
        float s = fut;
        #pragma unroll
        for (int d = 1; d < 32; d <<= 1) {
            float t = __shfl_down_sync(0xffffffffu, s, d);
            if (lane + d < 32) s += t;
        }
        if (lane == 0) wsum[warp] = s;
        __syncthreads();

        // warp 0: exclusive suffix over the 16 warp totals
        if (warp == 0) {
            float w = (lane < NWARP) ? wsum[lane] : 0.0f;
            float ws = w;
            #pragma unroll
            for (int d = 1; d < NWARP; d <<= 1) {
                float t = __shfl_down_sync(0xffffffffu, ws, d);
                if (lane + d < 32) ws += t;
            }
            if (lane < NWARP) wtail[lane] = ws - w;   // sum over warps > lane
        }
        __syncthreads();

        float mfm = (s - fut) + wtail[warp];          // sum_{j>n} fut[j]

        // per-column serial-scan coefficients
        float c1 = 1.0f - cs;
        pk[tid] = make_float4(c0, B1 * c1, M1 * mfm, M1);
        __syncthreads();

        // ---- prefetch + cs-independent work for next row (hides under scan) ----
        float xvn = 0.0f, mvn = 0.0f;
        if (m + 1 < NN) {
            xvn = xb[(m + 1) * NN + tid];
            mvn = mb[(m + 1) * NN + tid];
        }
        float sgn = 1.0f / (1.0f + expf(-xvn));
        float B1n = mvn * sgn;
        float M1n = mvn - B1n;
        float c0n = 1.0f - B1n;

        // ---- serial within-row scan (thread 0 only) ----
        if (tid == 0) {
            float r = 1.0f;            // r = 1 - row_sum
            float4 a0 = pk[0], a1 = pk[1], a2 = pk[2], a3 = pk[3];
            #pragma unroll 4
            for (int base = 0; base < NN; base += 8) {
                // prefetch chunk B while computing chunk A
                float4 b0 = pk[base + 4], b1 = pk[base + 5],
                       b2 = pk[base + 6], b3 = pk[base + 7];
                {
                    float v1, v2, w, rn;
                    v1 = a0.x * r; v2 = r - a0.y; w = fmaf(-a0.w, r, a0.z);
                    rn = fmaxf(v1, v2) + fminf(w, 0.0f);
                    rowp[base + 0] = r - rn; r = rn;
                    v1 = a1.x * r; v2 = r - a1.y; w = fmaf(-a1.w, r, a1.z);
                    rn = fmaxf(v1, v2) + fminf(w, 0.0f);
                    rowp[base + 1] = r - rn; r = rn;
                    v1 = a2.x * r; v2 = r - a2.y; w = fmaf(-a2.w, r, a2.z);
                    rn = fmaxf(v1, v2) + fminf(w, 0.0f);
                    rowp[base + 2] = r - rn; r = rn;
                    v1 = a3.x * r; v2 = r - a3.y; w = fmaf(-a3.w, r, a3.z);
                    rn = fmaxf(v1, v2) + fminf(w, 0.0f);
                    rowp[base + 3] = r - rn; r = rn;
                }
                // prefetch next chunk A (pad makes the tail read safe)
                a0 = pk[base + 8];  a1 = pk[base + 9];
                a2 = pk[base + 10]; a3 = pk[base + 11];
                {
                    float v1, v2, w, rn;
                    v1 = b0.x * r; v2 = r - b0.y; w = fmaf(-b0.w, r, b0.z);
                    rn = fmaxf(v1, v2) + fminf(w, 0.0f);
                    rowp[base + 4] = r - rn; r = rn;
                    v1 = b1.x * r; v2 = r - b1.y; w = fmaf(-b1.w, r, b1.z);
                    rn = fmaxf(v1, v2) + fminf(w, 0.0f);
                    rowp[base + 5] = r - rn; r = rn;
                    v1 = b2.x * r; v2 = r - b2.y; w = fmaf(-b2.w, r, b2.z);
                    rn = fmaxf(v1, v2) + fminf(w, 0.0f);
                    rowp[base + 6] = r - rn; r = rn;
                    v1 = b3.x * r; v2 = r - b3.y; w = fmaf(-b3.w, r, b3.z);
                    rn = fmaxf(v1, v2) + fminf(w, 0.0f);
                    rowp[base + 7] = r - rn; r = rn;
                }
            }
        }
        __syncthreads();

        // ---- consume row: update column sums, write output ----
        float p = rowp[tid];
        cs += p;
        ob[m * NN + tid] = p;

        // roll next-row state into place
        xv = xvn; mv = mvn; B1 = B1n; M1 = M1n; c0 = c0n;
        // safe without extra barrier: next row's first shared write (wsum)
        // happens before a sync that precedes thread 0's next rowp/pk access.
    }
}

extern "C" void kernel_launch(void* const* d_in, const int* in_sizes, int n_in,
                              void* d_out, int out_size)
{
    const float* x  = (const float*)d_in[0];
    const float* xm = (const float*)d_in[1];
    float* out = (float*)d_out;
    (void)in_sizes; (void)n_in; (void)out_size;

    stickbreak_kernel<<<NB, NN>>>(x, xm, out);
}

// round 9
// speedup vs baseline: 2.6268x; 1.0948x over previous
#include <cuda_runtime.h>
#include <math.h>

// StickBreaking: B=32, N=512. One CTA per batch; the N^2 recurrence is a
// single dependent FP chain per batch -> latency-bound.
// Pair-composition: serial loop does 256 steps of 2 columns each.
//   column 2k (f1): evaluated with the 14-cycle max/min chain
//   column 2k+1 (f2): 3-piece PWL applied as rn = fma(s2, y, t2), with the
//   piece selected by comparing r against PRE-INVERTED thresholds
//   Tc = f1^{-1}(V1), Td = f1^{-1}(V2)  -> selection runs parallel to f1.
// ~21 cyc / 2 columns vs ~16 / column before.

#define NB 32
#define NN 512
#define NP 256          // pairs == threads per block
#define NWARP 8

__global__ __launch_bounds__(NP, 1)
void stickbreak_kernel(const float* __restrict__ x,
                       const float* __restrict__ xm,
                       float* __restrict__ out)
{
    __shared__ float  wsum[NWARP];
    __shared__ float  wtail[NWARP];
    __shared__ float4 pd[NP + 4][3];   // per-pair serial record (padded)
    __shared__ float2 rowr[NP + 1];    // (r_in, y) per pair + final sentinel

    const int b    = blockIdx.x;
    const int tid  = threadIdx.x;
    const int lane = tid & 31;
    const int warp = tid >> 5;

    const float* xb = x  + (size_t)b * NN * NN;
    const float* mb = xm + (size_t)b * NN * NN;
    float*       ob = out + (size_t)b * NN * NN;

    // this thread owns columns 2*tid (f1) and 2*tid+1 (f2)
    float cs0 = 0.0f, cs1 = 0.0f;      // column sums

    // row 0: load + cs-independent precompute
    float2 xv = *(const float2*)(xb + 2 * tid);
    float2 mv = *(const float2*)(mb + 2 * tid);
    float sg0 = 1.0f / (1.0f + expf(-xv.x));
    float sg1 = 1.0f / (1.0f + expf(-xv.y));
    float B10 = mv.x * sg0, B11 = mv.y * sg1;     // b*mask
    float M10 = mv.x - B10, M11 = mv.y - B11;     // (1-b)*mask
    float c00 = 1.0f - B10, c01 = 1.0f - B11;

    for (int m = 0; m < NN; ++m) {
        // ---- fut + exact suffix sums over pairs ----
        float fut0 = fmaxf(0.0f, mv.x - cs0);
        float fut1 = fmaxf(0.0f, mv.y - cs1);
        float ps   = fut0 + fut1;

        float sfx = ps;                 // inclusive suffix within warp
        #pragma unroll
        for (int d = 1; d < 32; d <<= 1) {
            float t = __shfl_down_sync(0xffffffffu, sfx, d);
            if (lane + d < 32) sfx += t;
        }
        if (lane == 0) wsum[warp] = sfx;
        __syncthreads();

        if (warp == 0) {
            float w  = (lane < NWARP) ? wsum[lane] : 0.0f;
            float ws = w;
            #pragma unroll
            for (int d = 1; d < NWARP; d <<= 1) {
                float t = __shfl_down_sync(0xffffffffu, ws, d);
                if (lane + d < 32) ws += t;
            }
            if (lane < NWARP) wtail[lane] = ws - w;   // sum of warps > lane
        }
        __syncthreads();

        float tailp = (sfx - ps) + wtail[warp];       // sum over pairs > tid
        float mfm1  = tailp;                          // col 2k+1
        float mfm0  = tailp + fut1;                   // col 2k

        // ---- per-column pieces ----
        float c1a = 1.0f - cs0, c1b = 1.0f - cs1;
        float bc0 = B10 * c1a,  bc1 = B11 * c1b;
        float mz0 = M10 * mfm0, mz1 = M11 * mfm1;

        // f1 pieces: lo (c00, 0), mid (sm0, tm0), hi (sh0, th0)
        float Ua  = fminf(c1a, mfm0), Ub = fmaxf(c1a, mfm0);
        bool  cle0 = (c1a <= mfm0);
        float sm0 = cle0 ? 1.0f : (c00 - M10);
        float tm0 = cle0 ? (-bc0) : mz0;
        float sh0 = 1.0f - M10;
        float th0 = mz0 - bc0;

        // f2 pieces
        float Va  = fminf(c1b, mfm1), Vb = fmaxf(c1b, mfm1);
        bool  cle1 = (c1b <= mfm1);
        float sm1 = cle1 ? 1.0f : (c01 - M11);
        float tm1 = cle1 ? (-bc1) : mz1;
        float sh1 = 1.0f - M11;
        float th1 = mz1 - bc1;

        // invert f1 at f2's knots (f1 monotone nondecreasing)
        float y1 = c00 * Ua;                    // f1 at lower knot
        float y2 = fmaf(sh0, Ub, th0);          // f1 at upper knot
        float Tc = (Va <= y1) ? (Va / c00)
                 : (Va >= y2) ? ((Va - th0) / sh0)
                 : ((sm0 != 0.0f) ? ((Va - tm0) / sm0) : Ub);
        float Td = (Vb <= y1) ? (Vb / c00)
                 : (Vb >= y2) ? ((Vb - th0) / sh0)
                 : ((sm0 != 0.0f) ? ((Vb - tm0) / sm0) : Ub);

        pd[tid][0] = make_float4(c00, bc0, mz0, M10);
        pd[tid][1] = make_float4(Tc, Td, c01, sm1);
        pd[tid][2] = make_float4(sh1, tm1, th1, 0.0f);
        __syncthreads();

        // ---- prefetch next row (hides under the serial scan) ----
        float2 xvn = make_float2(0.0f, 0.0f);
        float2 mvn = make_float2(0.0f, 0.0f);
        if (m + 1 < NN) {
            xvn = *(const float2*)(xb + (m + 1) * NN + 2 * tid);
            mvn = *(const float2*)(mb + (m + 1) * NN + 2 * tid);
        }

        // ---- serial scan: 256 pair-steps ----
        if (tid == 0) {
            float r = 1.0f;             // r = 1 - row_sum
            float4 A0 = pd[0][0], A1 = pd[0][1], A2 = pd[0][2];
            float4 C0 = pd[1][0], C1 = pd[1][1], C2 = pd[1][2];
            #pragma unroll 2
            for (int k = 0; k < NP; k += 2) {
                {
                    bool  p1 = (r <= A1.x), p2 = (r <= A1.y);
                    float v1 = A0.x * r;
                    float v2 = r - A0.y;
                    float w  = fmaf(-A0.w, r, A0.z);
                    float yv = fmaxf(v1, v2) + fminf(w, 0.0f);
                    float s2 = p1 ? A1.z : (p2 ? A1.w : A2.x);
                    float t2 = p1 ? 0.0f : (p2 ? A2.y : A2.z);
                    rowr[k] = make_float2(r, yv);
                    r = fmaf(s2, yv, t2);
                }
                A0 = pd[k + 2][0]; A1 = pd[k + 2][1]; A2 = pd[k + 2][2];
                {
                    bool  p1 = (r <= C1.x), p2 = (r <= C1.y);
                    float v1 = C0.x * r;
                    float v2 = r - C0.y;
                    float w  = fmaf(-C0.w, r, C0.z);
                    float yv = fmaxf(v1, v2) + fminf(w, 0.0f);
                    float s2 = p1 ? C1.z : (p2 ? C1.w : C2.x);
                    float t2 = p1 ? 0.0f : (p2 ? C2.y : C2.z);
                    rowr[k + 1] = make_float2(r, yv);
                    r = fmaf(s2, yv, t2);
                }
                C0 = pd[k + 3][0]; C1 = pd[k + 3][1]; C2 = pd[k + 3][2];
            }
            rowr[NP] = make_float2(r, 0.0f);
        }
        __syncthreads();

        // ---- epilogue: recover p, update cs, store, roll next row ----
        float2 ry    = rowr[tid];
        float  rnext = rowr[tid + 1].x;
        float  p0 = ry.x - ry.y;        // col 2k
        float  p1 = ry.y - rnext;       // col 2k+1
        cs0 += p0;
        cs1 += p1;
        *(float2*)(ob + m * NN + 2 * tid) = make_float2(p0, p1);

        xv = xvn; mv = mvn;
        sg0 = 1.0f / (1.0f + expf(-xv.x));
        sg1 = 1.0f / (1.0f + expf(-xv.y));
        B10 = mv.x * sg0; B11 = mv.y * sg1;
        M10 = mv.x - B10; M11 = mv.y - B11;
        c00 = 1.0f - B10; c01 = 1.0f - B11;
        // no extra barrier needed: next row's first shared write (wsum) is
        // read only after the next sync, and pd/rowr rewrites are fenced by
        // the barriers preceding their consumers.
    }
}

extern "C" void kernel_launch(void* const* d_in, const int* in_sizes, int n_in,
                              void* d_out, int out_size)
{
    const float* x  = (const float*)d_in[0];
    const float* xm = (const float*)d_in[1];
    float* out = (float*)d_out;
    (void)in_sizes; (void)n_in; (void)out_size;

    stickbreak_kernel<<<NB, NP>>>(x, xm, out);
}